// round 5
// baseline (speedup 1.0000x reference)
#include <cuda_runtime.h>
#include <math.h>

#define NN 50000
#define EE 800000
#define ET (NN + EE)          // 850000 edges incl. self loops
#define NCH 98                // ceil(NN / 512)

// ---------------- scratch (device globals; no allocation allowed) ----------
__device__ float g_h1[(size_t)NN * 256];   // x @ W1
__device__ float g_h [(size_t)NN * 256];   // elu(gat1 out)  (input to layer 2)
__device__ float g_h2[(size_t)NN * 64];    // h @ W2
__device__ float g_as1[NN * 4];
__device__ float g_ad1[NN * 4];
__device__ float g_as2[NN];
__device__ float g_ad2[NN];
__device__ int   g_deg[NN];
__device__ int   g_off[NN + 1];
__device__ int   g_cur[NN];
__device__ int   g_srcid[ET];
__device__ int   g_csum[NCH];
__device__ int   g_ei64;                    // 1 if edge_index is int64 in memory

__device__ __forceinline__ float lrelu(float v) { return v >= 0.f ? v : 0.2f * v; }

__device__ __forceinline__ int load_edge(const int* __restrict__ ei, int j) {
    return g_ei64 ? ei[(size_t)j * 2] : ei[j];   // little-endian low word
}

// ---------------- diagnostics ------------------------------------------------
__global__ void k_flag(float* __restrict__ z, float v) { z[0] = v; }

__global__ void k_zcheck(float* __restrict__ z) {
    if (threadIdx.x == 0 && blockIdx.x == 0) {
        float s = 0.f;
        for (int i = 0; i < 64; i++) s += fabsf(z[i]);
        if (s < 1e-25f) z[0] = (g_off[NN - 1] == 0) ? 1e16f : 1e20f;
    }
}

// ---------------- dtype detector --------------------------------------------
__global__ void k_detect(const int* __restrict__ ei) {
    if (threadIdx.x == 0 && blockIdx.x == 0) {
        int odd_nz = 0, even_nz = 0;
        for (int j = 0; j < 256; j += 2) {
            if (ei[j]     != 0) even_nz++;
            if (ei[j + 1] != 0) odd_nz++;
        }
        g_ei64 = (odd_nz == 0 && even_nz > 0) ? 1 : 0;
    }
}

__global__ void k_zero_out(float* __restrict__ o, int n) {
    int i = blockIdx.x * blockDim.x + threadIdx.x;
    if (i < n) o[i] = 0.f;
}

// ---------------- CSR build -------------------------------------------------
__global__ void k_zero_deg() {
    int i = blockIdx.x * blockDim.x + threadIdx.x;
    if (i < NN) g_deg[i] = 0;
}

__global__ void k_count(const int* __restrict__ ei) {
    int e = blockIdx.x * blockDim.x + threadIdx.x;
    if (e >= ET) return;
    int dst = (e < EE) ? load_edge(ei, EE + e) : (e - EE);
    if ((unsigned)dst < (unsigned)NN) atomicAdd(&g_deg[dst], 1);
}

__global__ void k_scan_chunk() {
    __shared__ int s[512];
    int tid = threadIdx.x;
    int i = blockIdx.x * 512 + tid;
    int v = (i < NN) ? g_deg[i] : 0;
    s[tid] = v;
    __syncthreads();
    for (int o = 1; o < 512; o <<= 1) {
        int t = (tid >= o) ? s[tid - o] : 0;
        __syncthreads();
        s[tid] += t;
        __syncthreads();
    }
    if (i < NN) g_off[i] = s[tid] - v;
    if (tid == 511) g_csum[blockIdx.x] = s[511];
}

__global__ void k_scan_mid() {
    if (threadIdx.x == 0 && blockIdx.x == 0) {
        int acc = 0;
        for (int i = 0; i < NCH; i++) { int v = g_csum[i]; g_csum[i] = acc; acc += v; }
    }
}

__global__ void k_scan_add() {
    int i = blockIdx.x * 512 + threadIdx.x;
    if (i < NN) {
        int o = g_off[i] + g_csum[blockIdx.x];
        g_off[i] = o;
        g_cur[i] = o;
    }
    if (i == 0) g_off[NN] = ET;
}

__global__ void k_scatter(const int* __restrict__ ei) {
    int e = blockIdx.x * blockDim.x + threadIdx.x;
    if (e >= ET) return;
    int s, d;
    if (e < EE) { s = load_edge(ei, e); d = load_edge(ei, EE + e); }
    else        { s = d = e - EE; }
    if ((unsigned)d >= (unsigned)NN || (unsigned)s >= (unsigned)NN) return;
    int p = atomicAdd(&g_cur[d], 1);
    if ((unsigned)p < (unsigned)ET) g_srcid[p] = s;
}

// ---------------- GEMM1: g_h1 = x @ W1  (M=NN, K=128, N=256) ---------------
// NOTE: device globals referenced IN DEVICE CODE (never passed from host).
__global__ void k_gemm1(const float* __restrict__ A, const float* __restrict__ B) {
    const int K = 128, Nc = 256;
    __shared__ float As[64][33];
    __shared__ float Bs[32][65];
    int bm = blockIdx.y * 64, bn = blockIdx.x * 64;
    int tid = threadIdx.x;
    int tx = tid & 15, ty = tid >> 4;
    float acc[4][4] = {};
    #pragma unroll
    for (int k0 = 0; k0 < K; k0 += 32) {
        #pragma unroll
        for (int i = tid; i < 64 * 32; i += 256) {
            int r = i >> 5, c = i & 31;
            int gr = bm + r;
            As[r][c] = (gr < NN) ? A[(size_t)gr * K + k0 + c] : 0.f;
        }
        #pragma unroll
        for (int i = tid; i < 32 * 64; i += 256) {
            int r = i >> 6, c = i & 63;
            Bs[r][c] = B[(size_t)(k0 + r) * Nc + bn + c];
        }
        __syncthreads();
        #pragma unroll
        for (int k = 0; k < 32; k++) {
            float a[4], b[4];
            #pragma unroll
            for (int u = 0; u < 4; u++) { a[u] = As[ty * 4 + u][k]; b[u] = Bs[k][tx * 4 + u]; }
            #pragma unroll
            for (int u = 0; u < 4; u++)
                #pragma unroll
                for (int v = 0; v < 4; v++) acc[u][v] += a[u] * b[v];
        }
        __syncthreads();
    }
    #pragma unroll
    for (int u = 0; u < 4; u++) {
        int gr = bm + ty * 4 + u;
        if (gr < NN)
            #pragma unroll
            for (int v = 0; v < 4; v++) g_h1[(size_t)gr * Nc + bn + tx * 4 + v] = acc[u][v];
    }
}

// ---------------- GEMM2: g_h2 = g_h @ W2 (M=NN, K=256, N=64) ---------------
__global__ void k_gemm2(const float* __restrict__ B) {
    const int K = 256, Nc = 64;
    __shared__ float As[64][33];
    __shared__ float Bs[32][65];
    int bm = blockIdx.y * 64, bn = 0;
    int tid = threadIdx.x;
    int tx = tid & 15, ty = tid >> 4;
    float acc[4][4] = {};
    #pragma unroll
    for (int k0 = 0; k0 < K; k0 += 32) {
        #pragma unroll
        for (int i = tid; i < 64 * 32; i += 256) {
            int r = i >> 5, c = i & 31;
            int gr = bm + r;
            As[r][c] = (gr < NN) ? g_h[(size_t)gr * K + k0 + c] : 0.f;
        }
        #pragma unroll
        for (int i = tid; i < 32 * 64; i += 256) {
            int r = i >> 6, c = i & 63;
            Bs[r][c] = B[(size_t)(k0 + r) * Nc + bn + c];
        }
        __syncthreads();
        #pragma unroll
        for (int k = 0; k < 32; k++) {
            float a[4], b[4];
            #pragma unroll
            for (int u = 0; u < 4; u++) { a[u] = As[ty * 4 + u][k]; b[u] = Bs[k][tx * 4 + u]; }
            #pragma unroll
            for (int u = 0; u < 4; u++)
                #pragma unroll
                for (int v = 0; v < 4; v++) acc[u][v] += a[u] * b[v];
        }
        __syncthreads();
    }
    #pragma unroll
    for (int u = 0; u < 4; u++) {
        int gr = bm + ty * 4 + u;
        if (gr < NN)
            #pragma unroll
            for (int v = 0; v < 4; v++) g_h2[(size_t)gr * Nc + bn + tx * 4 + v] = acc[u][v];
    }
}

// ---------------- attention coefficients (layer 1) --------------------------
__global__ void k_att1(const float* __restrict__ att_s, const float* __restrict__ att_d) {
    int w = (blockIdx.x * blockDim.x + threadIdx.x) >> 5;
    int lane = threadIdx.x & 31;
    if (w >= NN) return;
    int c = lane * 8;
    const float4* hp = (const float4*)&g_h1[(size_t)w * 256 + c];
    float4 h0 = hp[0], h1 = hp[1];
    const float4* sp = (const float4*)&att_s[c];
    const float4* dp = (const float4*)&att_d[c];
    float4 s0 = sp[0], s1 = sp[1], d0 = dp[0], d1 = dp[1];
    float ps = h0.x * s0.x + h0.y * s0.y + h0.z * s0.z + h0.w * s0.w
             + h1.x * s1.x + h1.y * s1.y + h1.z * s1.z + h1.w * s1.w;
    float pd = h0.x * d0.x + h0.y * d0.y + h0.z * d0.z + h0.w * d0.w
             + h1.x * d1.x + h1.y * d1.y + h1.z * d1.z + h1.w * d1.w;
    #pragma unroll
    for (int o = 1; o < 8; o <<= 1) {
        ps += __shfl_xor_sync(0xffffffffu, ps, o);
        pd += __shfl_xor_sync(0xffffffffu, pd, o);
    }
    if ((lane & 7) == 0) {
        int h = lane >> 3;
        g_as1[w * 4 + h] = ps;
        g_ad1[w * 4 + h] = pd;
    }
}

// ---------------- fused GAT layer-1 aggregation (warp per dst node) --------
__global__ void k_agg1(const float* __restrict__ b1) {
    int node = (blockIdx.x * blockDim.x + threadIdx.x) >> 5;
    int lane = threadIdx.x & 31;
    if (node >= NN) return;
    int beg = g_off[node], end = g_off[node + 1];
    float ad0 = g_ad1[node * 4 + 0], ad1 = g_ad1[node * 4 + 1];
    float ad2 = g_ad1[node * 4 + 2], ad3 = g_ad1[node * 4 + 3];

    float m0 = -3.4e38f, m1 = -3.4e38f, m2 = -3.4e38f, m3 = -3.4e38f;
    for (int i = beg + lane; i < end; i += 32) {
        int s = g_srcid[i];
        m0 = fmaxf(m0, lrelu(g_as1[s * 4 + 0] + ad0));
        m1 = fmaxf(m1, lrelu(g_as1[s * 4 + 1] + ad1));
        m2 = fmaxf(m2, lrelu(g_as1[s * 4 + 2] + ad2));
        m3 = fmaxf(m3, lrelu(g_as1[s * 4 + 3] + ad3));
    }
    #pragma unroll
    for (int o = 16; o > 0; o >>= 1) {
        m0 = fmaxf(m0, __shfl_xor_sync(0xffffffffu, m0, o));
        m1 = fmaxf(m1, __shfl_xor_sync(0xffffffffu, m1, o));
        m2 = fmaxf(m2, __shfl_xor_sync(0xffffffffu, m2, o));
        m3 = fmaxf(m3, __shfl_xor_sync(0xffffffffu, m3, o));
    }
    int hh = lane >> 3;
    float mxh = (hh == 0) ? m0 : (hh == 1) ? m1 : (hh == 2) ? m2 : m3;
    float adh = (hh == 0) ? ad0 : (hh == 1) ? ad1 : (hh == 2) ? ad2 : ad3;

    float a0=0,a1=0,a2=0,a3=0,a4=0,a5=0,a6=0,a7=0;
    float den = 0.f;
    for (int i = beg; i < end; i++) {
        int s = g_srcid[i];
        float w = expf(lrelu(g_as1[s * 4 + hh] + adh) - mxh);
        den += w;
        const float4* hp = (const float4*)&g_h1[(size_t)s * 256 + lane * 8];
        float4 ha = hp[0], hb = hp[1];
        a0 += ha.x * w; a1 += ha.y * w; a2 += ha.z * w; a3 += ha.w * w;
        a4 += hb.x * w; a5 += hb.y * w; a6 += hb.z * w; a7 += hb.w * w;
    }
    float inv = 1.f / (den + 1e-16f);
    const float4* bp = (const float4*)&b1[lane * 8];
    float4 bb0 = bp[0], bb1 = bp[1];
    float o0 = a0*inv+bb0.x, o1 = a1*inv+bb0.y, o2 = a2*inv+bb0.z, o3 = a3*inv+bb0.w;
    float o4 = a4*inv+bb1.x, o5 = a5*inv+bb1.y, o6 = a6*inv+bb1.z, o7 = a7*inv+bb1.w;
    o0 = o0 > 0.f ? o0 : expm1f(o0); o1 = o1 > 0.f ? o1 : expm1f(o1);
    o2 = o2 > 0.f ? o2 : expm1f(o2); o3 = o3 > 0.f ? o3 : expm1f(o3);
    o4 = o4 > 0.f ? o4 : expm1f(o4); o5 = o5 > 0.f ? o5 : expm1f(o5);
    o6 = o6 > 0.f ? o6 : expm1f(o6); o7 = o7 > 0.f ? o7 : expm1f(o7);
    float4* op = (float4*)&g_h[(size_t)node * 256 + lane * 8];
    op[0] = make_float4(o0, o1, o2, o3);
    op[1] = make_float4(o4, o5, o6, o7);
}

// ---------------- attention coefficients (layer 2, 1 head) -----------------
__global__ void k_att2(const float* __restrict__ att_s, const float* __restrict__ att_d) {
    int w = (blockIdx.x * blockDim.x + threadIdx.x) >> 5;
    int lane = threadIdx.x & 31;
    if (w >= NN) return;
    float2 h = *(const float2*)&g_h2[(size_t)w * 64 + lane * 2];
    float2 as = *(const float2*)&att_s[lane * 2];
    float2 ad = *(const float2*)&att_d[lane * 2];
    float ps = h.x * as.x + h.y * as.y;
    float pd = h.x * ad.x + h.y * ad.y;
    #pragma unroll
    for (int o = 16; o > 0; o >>= 1) {
        ps += __shfl_xor_sync(0xffffffffu, ps, o);
        pd += __shfl_xor_sync(0xffffffffu, pd, o);
    }
    if (lane == 0) { g_as2[w] = ps; g_ad2[w] = pd; }
}

// ---------------- fused GAT layer-2 aggregation + L2 normalize -------------
__global__ void k_agg2(const float* __restrict__ b2, float* __restrict__ zout) {
    int node = (blockIdx.x * blockDim.x + threadIdx.x) >> 5;
    int lane = threadIdx.x & 31;
    if (node >= NN) return;
    int beg = g_off[node], end = g_off[node + 1];
    float ad = g_ad2[node];

    float mx = -3.4e38f;
    for (int i = beg + lane; i < end; i += 32)
        mx = fmaxf(mx, lrelu(g_as2[g_srcid[i]] + ad));
    #pragma unroll
    for (int o = 16; o > 0; o >>= 1)
        mx = fmaxf(mx, __shfl_xor_sync(0xffffffffu, mx, o));

    float acc0 = 0.f, acc1 = 0.f, den = 0.f;
    for (int i = beg; i < end; i++) {
        int s = g_srcid[i];
        float w = expf(lrelu(g_as2[s] + ad) - mx);
        den += w;
        float2 h = *(const float2*)&g_h2[(size_t)s * 64 + lane * 2];
        acc0 += h.x * w; acc1 += h.y * w;
    }
    float inv = 1.f / (den + 1e-16f);
    float2 bb = *(const float2*)&b2[lane * 2];
    float z0 = acc0 * inv + bb.x;
    float z1 = acc1 * inv + bb.y;
    float ss = z0 * z0 + z1 * z1;
    #pragma unroll
    for (int o = 16; o > 0; o >>= 1)
        ss += __shfl_xor_sync(0xffffffffu, ss, o);
    float invn = 1.f / fmaxf(sqrtf(ss), 1e-12f);
    float2* zp = (float2*)&zout[(size_t)node * 64 + lane * 2];
    *zp = make_float2(z0 * invn, z1 * invn);
}

// ---------------- decoder: x_hat = elu(z@dW1+db1)@dW2+db2 ------------------
__global__ void k_decoder(const float* __restrict__ z,
                          const float* __restrict__ dW1, const float* __restrict__ db1,
                          const float* __restrict__ dW2, const float* __restrict__ db2,
                          float* __restrict__ xhat) {
    __shared__ float sW1[64 * 64];
    __shared__ float sb1[64];
    __shared__ float sz[64];
    __shared__ float st[64];
    int tid = threadIdx.x;  // 128 threads
    for (int i = tid; i < 64 * 64; i += 128) sW1[i] = dW1[i];
    if (tid < 64) sb1[tid] = db1[tid];
    float b2v = db2[tid];
    __syncthreads();
    for (int node = blockIdx.x; node < NN; node += gridDim.x) {
        if (tid < 64) sz[tid] = z[(size_t)node * 64 + tid];
        __syncthreads();
        if (tid < 64) {
            float t = sb1[tid];
            #pragma unroll 8
            for (int k = 0; k < 64; k++) t += sz[k] * sW1[k * 64 + tid];
            st[tid] = t > 0.f ? t : expm1f(t);
        }
        __syncthreads();
        float o = b2v;
        #pragma unroll 8
        for (int j = 0; j < 64; j++) o += st[j] * dW2[(size_t)j * 128 + tid];
        xhat[(size_t)node * 128 + tid] = o;
        __syncthreads();
    }
}

// ---------------- launcher ---------------------------------------------------
extern "C" void kernel_launch(void* const* d_in, const int* in_sizes, int n_in,
                              void* d_out, int out_size) {
    float* z = (float*)d_out;                       // [NN,64] (output 0)
    float* xhat = (out_size >= 9600000) ? (z + (size_t)NN * 64) : 0;

    k_zero_out<<<(out_size + 511) / 512, 512>>>((float*)d_out, out_size);

    // ---- input resolution: positional (dict order) verified by sizes ----
    static const int expect[14] = {6400000, 1600000, 32768, 256, 256, 256,
                                   16384, 64, 64, 64, 4096, 64, 8192, 128};
    bool positionalOK = (n_in == 14);
    if (positionalOK) {
        for (int i = 0; i < 14; i++) {
            int s = in_sizes[i];
            if (s != expect[i] && !(i == 1 && s == 3200000)) { positionalOK = false; break; }
        }
    }

    const float *x = 0, *W1 = 0, *W2 = 0, *dW1 = 0, *dW2 = 0, *db2 = 0;
    const float *atts1 = 0, *attd1 = 0, *b1 = 0, *atts2 = 0, *attd2 = 0, *b2 = 0, *db1 = 0;
    const int* ei = 0;

    if (positionalOK) {
        x     = (const float*)d_in[0];
        ei    = (const int*)  d_in[1];
        W1    = (const float*)d_in[2];
        atts1 = (const float*)d_in[3];
        attd1 = (const float*)d_in[4];
        b1    = (const float*)d_in[5];
        W2    = (const float*)d_in[6];
        atts2 = (const float*)d_in[7];
        attd2 = (const float*)d_in[8];
        b2    = (const float*)d_in[9];
        dW1   = (const float*)d_in[10];
        db1   = (const float*)d_in[11];
        dW2   = (const float*)d_in[12];
        db2   = (const float*)d_in[13];
    } else {
        const float* g256[3] = {0, 0, 0};
        const float* g64[4]  = {0, 0, 0, 0};
        int n256 = 0, n64 = 0;
        for (int i = 0; i < n_in; i++) {
            int s = in_sizes[i];
            const float* p = (const float*)d_in[i];
            if      (s == 6400000) x   = p;
            else if (s == 1600000 || s == 3200000) ei = (const int*)d_in[i];
            else if (s == 32768)   W1  = p;
            else if (s == 16384)   W2  = p;
            else if (s == 4096)    dW1 = p;
            else if (s == 8192)    dW2 = p;
            else if (s == 128)     db2 = p;
            else if (s == 256 && n256 < 3) g256[n256++] = p;
            else if (s == 64  && n64  < 4) g64[n64++]   = p;
        }
        bool dictLike = (n_in > 0 && in_sizes[0] == 6400000);
        atts1 = g256[dictLike ? 0 : 1];
        attd1 = g256[dictLike ? 1 : 0];
        b1    = g256[2];
        atts2 = g64[dictLike ? 0 : 1];
        attd2 = g64[dictLike ? 1 : 0];
        b2    = g64[2];
        db1   = g64[3];
        if (!x || !ei || !W1 || !W2 || !dW1 || !dW2 || !db2 || n256 < 3 || n64 < 4) {
            k_flag<<<1, 1>>>(z, 1e12f);
            return;
        }
    }

    k_detect<<<1, 32>>>(ei);

    // --- CSR build ---
    k_zero_deg<<<(NN + 255) / 256, 256>>>();
    k_count<<<(ET + 255) / 256, 256>>>(ei);
    k_scan_chunk<<<NCH, 512>>>();
    k_scan_mid<<<1, 32>>>();
    k_scan_add<<<NCH, 512>>>();
    k_scatter<<<(ET + 255) / 256, 256>>>(ei);

    // --- layer 1 ---
    {
        dim3 g(4, (NN + 63) / 64);
        k_gemm1<<<g, 256>>>(x, W1);
    }
    k_att1<<<(NN * 32 + 255) / 256, 256>>>(atts1, attd1);
    k_agg1<<<(NN * 32 + 255) / 256, 256>>>(b1);

    // --- layer 2 ---
    {
        dim3 g(1, (NN + 63) / 64);
        k_gemm2<<<g, 256>>>(W2);
    }
    k_att2<<<(NN * 32 + 255) / 256, 256>>>(atts2, attd2);
    k_agg2<<<(NN * 32 + 255) / 256, 256>>>(b2, z);

    // --- diagnostic: if z is still all-zero, encode failing stage ---
    k_zcheck<<<1, 1>>>(z);

    // --- decoder ---
    if (xhat)
        k_decoder<<<1024, 128>>>(z, dW1, db1, dW2, db2, xhat);
}

// round 6
// speedup vs baseline: 1.2051x; 1.2051x over previous
#include <cuda_runtime.h>
#include <math.h>

#define NN 50000
#define EE 800000
#define ET (NN + EE)          // 850000 edges incl. self loops
#define NCH 98                // ceil(NN / 512)

// ---------------- scratch (device globals; no allocation allowed) ----------
__device__ float g_h1[(size_t)NN * 256];   // x @ W1
__device__ float g_h [(size_t)NN * 256];   // elu(gat1 out)  (input to layer 2)
__device__ float g_h2[(size_t)NN * 64];    // h @ W2
__device__ float g_as1[NN * 4];
__device__ float g_ad1[NN * 4];
__device__ float g_as2[NN];
__device__ float g_ad2[NN];
__device__ int   g_deg[NN];
__device__ int   g_off[NN + 1];
__device__ int   g_cur[NN];
__device__ int   g_srcid[ET];
__device__ int   g_csum[NCH];
__device__ int   g_ei64;                    // 1 if edge_index is int64 in memory

__device__ __forceinline__ float lrelu(float v) { return v >= 0.f ? v : 0.2f * v; }

__device__ __forceinline__ int load_edge(const int* __restrict__ ei, int j) {
    return g_ei64 ? ei[(size_t)j * 2] : ei[j];   // little-endian low word
}

__global__ void k_flag(float* __restrict__ z, float v) { z[0] = v; }

__global__ void k_zero_out(float* __restrict__ o, int n) {
    int i = blockIdx.x * blockDim.x + threadIdx.x;
    if (i < n) o[i] = 0.f;
}

// ---------------- dtype detector --------------------------------------------
__global__ void k_detect(const int* __restrict__ ei) {
    if (threadIdx.x == 0 && blockIdx.x == 0) {
        int odd_nz = 0, even_nz = 0;
        for (int j = 0; j < 256; j += 2) {
            if (ei[j]     != 0) even_nz++;
            if (ei[j + 1] != 0) odd_nz++;
        }
        g_ei64 = (odd_nz == 0 && even_nz > 0) ? 1 : 0;
    }
}

// ---------------- CSR build -------------------------------------------------
__global__ void k_zero_deg() {
    int i = blockIdx.x * blockDim.x + threadIdx.x;
    if (i < NN) g_deg[i] = 0;
}

__global__ void k_count(const int* __restrict__ ei) {
    int e = blockIdx.x * blockDim.x + threadIdx.x;
    if (e >= ET) return;
    int dst = (e < EE) ? load_edge(ei, EE + e) : (e - EE);
    if ((unsigned)dst < (unsigned)NN) atomicAdd(&g_deg[dst], 1);
}

__global__ void k_scan_chunk() {
    __shared__ int s[512];
    int tid = threadIdx.x;
    int i = blockIdx.x * 512 + tid;
    int v = (i < NN) ? g_deg[i] : 0;
    s[tid] = v;
    __syncthreads();
    for (int o = 1; o < 512; o <<= 1) {
        int t = (tid >= o) ? s[tid - o] : 0;
        __syncthreads();
        s[tid] += t;
        __syncthreads();
    }
    if (i < NN) g_off[i] = s[tid] - v;
    if (tid == 511) g_csum[blockIdx.x] = s[511];
}

__global__ void k_scan_mid() {
    if (threadIdx.x == 0 && blockIdx.x == 0) {
        int acc = 0;
        for (int i = 0; i < NCH; i++) { int v = g_csum[i]; g_csum[i] = acc; acc += v; }
    }
}

__global__ void k_scan_add() {
    int i = blockIdx.x * 512 + threadIdx.x;
    if (i < NN) {
        int o = g_off[i] + g_csum[blockIdx.x];
        g_off[i] = o;
        g_cur[i] = o;
    }
    if (i == 0) g_off[NN] = ET;
}

__global__ void k_scatter(const int* __restrict__ ei) {
    int e = blockIdx.x * blockDim.x + threadIdx.x;
    if (e >= ET) return;
    int s, d;
    if (e < EE) { s = load_edge(ei, e); d = load_edge(ei, EE + e); }
    else        { s = d = e - EE; }
    if ((unsigned)d >= (unsigned)NN || (unsigned)s >= (unsigned)NN) return;
    int p = atomicAdd(&g_cur[d], 1);
    if ((unsigned)p < (unsigned)ET) g_srcid[p] = s;
}

// ---------------- SGEMM: BM=128, BN=64, BK=16, 256 thr, 8x4 micro ----------
__global__ void k_gemm(const float* __restrict__ A, const float* __restrict__ B,
                       float* __restrict__ C, int M, int K, int Nc) {
    __shared__ float As[16][132];   // transposed tile: As[k][m]
    __shared__ float Bs[16][68];
    int bm = blockIdx.y * 128, bn = blockIdx.x * 64;
    int tid = threadIdx.x;
    int tx = tid & 15, ty = tid >> 4;      // tx: 4-col group, ty: 8-row group
    float acc[8][4] = {};
    for (int k0 = 0; k0 < K; k0 += 16) {
        #pragma unroll
        for (int i = tid; i < 128 * 16; i += 256) {
            int r = i >> 4, c = i & 15;
            int gr = bm + r;
            As[c][r] = (gr < M) ? A[(size_t)gr * K + k0 + c] : 0.f;
        }
        #pragma unroll
        for (int i = tid; i < 16 * 64; i += 256) {
            int r = i >> 6, c = i & 63;
            Bs[r][c] = B[(size_t)(k0 + r) * Nc + bn + c];
        }
        __syncthreads();
        #pragma unroll
        for (int k = 0; k < 16; k++) {
            float a[8], b[4];
            #pragma unroll
            for (int u = 0; u < 8; u++) a[u] = As[k][ty * 8 + u];
            #pragma unroll
            for (int v = 0; v < 4; v++) b[v] = Bs[k][tx * 4 + v];
            #pragma unroll
            for (int u = 0; u < 8; u++)
                #pragma unroll
                for (int v = 0; v < 4; v++) acc[u][v] += a[u] * b[v];
        }
        __syncthreads();
    }
    #pragma unroll
    for (int u = 0; u < 8; u++) {
        int gr = bm + ty * 8 + u;
        if (gr < M) {
            float4 o = make_float4(acc[u][0], acc[u][1], acc[u][2], acc[u][3]);
            *(float4*)&C[(size_t)gr * Nc + bn + tx * 4] = o;
        }
    }
}

// ---------------- attention coefficients (layer 1) --------------------------
__global__ void k_att1(const float* __restrict__ att_s, const float* __restrict__ att_d) {
    int w = (blockIdx.x * blockDim.x + threadIdx.x) >> 5;
    int lane = threadIdx.x & 31;
    if (w >= NN) return;
    int c = lane * 8;
    const float4* hp = (const float4*)&g_h1[(size_t)w * 256 + c];
    float4 h0 = hp[0], h1 = hp[1];
    const float4* sp = (const float4*)&att_s[c];
    const float4* dp = (const float4*)&att_d[c];
    float4 s0 = sp[0], s1 = sp[1], d0 = dp[0], d1 = dp[1];
    float ps = h0.x * s0.x + h0.y * s0.y + h0.z * s0.z + h0.w * s0.w
             + h1.x * s1.x + h1.y * s1.y + h1.z * s1.z + h1.w * s1.w;
    float pd = h0.x * d0.x + h0.y * d0.y + h0.z * d0.z + h0.w * d0.w
             + h1.x * d1.x + h1.y * d1.y + h1.z * d1.z + h1.w * d1.w;
    #pragma unroll
    for (int o = 1; o < 8; o <<= 1) {
        ps += __shfl_xor_sync(0xffffffffu, ps, o);
        pd += __shfl_xor_sync(0xffffffffu, pd, o);
    }
    if ((lane & 7) == 0) {
        int h = lane >> 3;
        g_as1[w * 4 + h] = ps;
        g_ad1[w * 4 + h] = pd;
    }
}

// ---- fused GAT layer-1 aggregation (warp/node, single pass, no max) -------
__global__ void k_agg1(const float* __restrict__ b1) {
    int node = (blockIdx.x * blockDim.x + threadIdx.x) >> 5;
    int lane = threadIdx.x & 31;
    if (node >= NN) return;
    int beg = g_off[node], end = g_off[node + 1];
    int hh = lane >> 3;
    float adh = g_ad1[node * 4 + hh];

    float a0=0,a1=0,a2=0,a3=0,a4=0,a5=0,a6=0,a7=0;
    float den = 0.f;
    for (int i = beg; i < end; i++) {
        int s = g_srcid[i];
        float w = __expf(lrelu(g_as1[s * 4 + hh] + adh));
        den += w;
        const float4* hp = (const float4*)&g_h1[(size_t)s * 256 + lane * 8];
        float4 ha = hp[0], hb = hp[1];
        a0 += ha.x * w; a1 += ha.y * w; a2 += ha.z * w; a3 += ha.w * w;
        a4 += hb.x * w; a5 += hb.y * w; a6 += hb.z * w; a7 += hb.w * w;
    }
    float inv = 1.f / (den + 1e-16f);
    const float4* bp = (const float4*)&b1[lane * 8];
    float4 bb0 = bp[0], bb1 = bp[1];
    float o0 = a0*inv+bb0.x, o1 = a1*inv+bb0.y, o2 = a2*inv+bb0.z, o3 = a3*inv+bb0.w;
    float o4 = a4*inv+bb1.x, o5 = a5*inv+bb1.y, o6 = a6*inv+bb1.z, o7 = a7*inv+bb1.w;
    o0 = o0 > 0.f ? o0 : __expf(o0) - 1.f; o1 = o1 > 0.f ? o1 : __expf(o1) - 1.f;
    o2 = o2 > 0.f ? o2 : __expf(o2) - 1.f; o3 = o3 > 0.f ? o3 : __expf(o3) - 1.f;
    o4 = o4 > 0.f ? o4 : __expf(o4) - 1.f; o5 = o5 > 0.f ? o5 : __expf(o5) - 1.f;
    o6 = o6 > 0.f ? o6 : __expf(o6) - 1.f; o7 = o7 > 0.f ? o7 : __expf(o7) - 1.f;
    float4* op = (float4*)&g_h[(size_t)node * 256 + lane * 8];
    op[0] = make_float4(o0, o1, o2, o3);
    op[1] = make_float4(o4, o5, o6, o7);
}

// ---------------- attention coefficients (layer 2, 1 head) -----------------
__global__ void k_att2(const float* __restrict__ att_s, const float* __restrict__ att_d) {
    int w = (blockIdx.x * blockDim.x + threadIdx.x) >> 5;
    int lane = threadIdx.x & 31;
    if (w >= NN) return;
    float2 h = *(const float2*)&g_h2[(size_t)w * 64 + lane * 2];
    float2 as = *(const float2*)&att_s[lane * 2];
    float2 ad = *(const float2*)&att_d[lane * 2];
    float ps = h.x * as.x + h.y * as.y;
    float pd = h.x * ad.x + h.y * ad.y;
    #pragma unroll
    for (int o = 16; o > 0; o >>= 1) {
        ps += __shfl_xor_sync(0xffffffffu, ps, o);
        pd += __shfl_xor_sync(0xffffffffu, pd, o);
    }
    if (lane == 0) { g_as2[w] = ps; g_ad2[w] = pd; }
}

// ---- fused GAT layer-2 aggregation + L2 normalize (single pass) -----------
__global__ void k_agg2(const float* __restrict__ b2, float* __restrict__ zout) {
    int node = (blockIdx.x * blockDim.x + threadIdx.x) >> 5;
    int lane = threadIdx.x & 31;
    if (node >= NN) return;
    int beg = g_off[node], end = g_off[node + 1];
    float ad = g_ad2[node];

    float acc0 = 0.f, acc1 = 0.f, den = 0.f;
    for (int i = beg; i < end; i++) {
        int s = g_srcid[i];
        float w = __expf(lrelu(g_as2[s] + ad));
        den += w;
        float2 h = *(const float2*)&g_h2[(size_t)s * 64 + lane * 2];
        acc0 += h.x * w; acc1 += h.y * w;
    }
    float inv = 1.f / (den + 1e-16f);
    float2 bb = *(const float2*)&b2[lane * 2];
    float z0 = acc0 * inv + bb.x;
    float z1 = acc1 * inv + bb.y;
    float ss = z0 * z0 + z1 * z1;
    #pragma unroll
    for (int o = 16; o > 0; o >>= 1)
        ss += __shfl_xor_sync(0xffffffffu, ss, o);
    float invn = 1.f / fmaxf(sqrtf(ss), 1e-12f);
    float2* zp = (float2*)&zout[(size_t)node * 64 + lane * 2];
    *zp = make_float2(z0 * invn, z1 * invn);
}

// ---------------- decoder: x_hat = elu(z@dW1+db1)@dW2+db2 ------------------
__global__ void k_decoder(const float* __restrict__ z,
                          const float* __restrict__ dW1, const float* __restrict__ db1,
                          const float* __restrict__ dW2, const float* __restrict__ db2,
                          float* __restrict__ xhat) {
    __shared__ float sW1[64 * 64];
    __shared__ float sb1[64];
    __shared__ float sz[64];
    __shared__ float st[64];
    int tid = threadIdx.x;  // 128 threads
    for (int i = tid; i < 64 * 64; i += 128) sW1[i] = dW1[i];
    if (tid < 64) sb1[tid] = db1[tid];
    float b2v = db2[tid];
    __syncthreads();
    for (int node = blockIdx.x; node < NN; node += gridDim.x) {
        if (tid < 64) sz[tid] = z[(size_t)node * 64 + tid];
        __syncthreads();
        if (tid < 64) {
            float t = sb1[tid];
            #pragma unroll 8
            for (int k = 0; k < 64; k++) t += sz[k] * sW1[k * 64 + tid];
            st[tid] = t > 0.f ? t : __expf(t) - 1.f;
        }
        __syncthreads();
        float o = b2v;
        #pragma unroll 8
        for (int j = 0; j < 64; j++) o += st[j] * dW2[(size_t)j * 128 + tid];
        xhat[(size_t)node * 128 + tid] = o;
        __syncthreads();
    }
}

// ---------------- launcher ---------------------------------------------------
extern "C" void kernel_launch(void* const* d_in, const int* in_sizes, int n_in,
                              void* d_out, int out_size) {
    float* z = (float*)d_out;                       // [NN,64] (output 0)
    float* xhat = (out_size >= 9600000) ? (z + (size_t)NN * 64) : 0;

    if (out_size != 9600000)   // only pad-fill when layout has slack
        k_zero_out<<<(out_size + 511) / 512, 512>>>((float*)d_out, out_size);

    // real device addresses of the scratch globals (host-passable)
    float *p_h1 = 0, *p_h = 0, *p_h2 = 0;
    cudaGetSymbolAddress((void**)&p_h1, g_h1);
    cudaGetSymbolAddress((void**)&p_h,  g_h);
    cudaGetSymbolAddress((void**)&p_h2, g_h2);

    // ---- input resolution: positional (dict order) verified by sizes ----
    static const int expect[14] = {6400000, 1600000, 32768, 256, 256, 256,
                                   16384, 64, 64, 64, 4096, 64, 8192, 128};
    bool positionalOK = (n_in == 14);
    if (positionalOK) {
        for (int i = 0; i < 14; i++) {
            int s = in_sizes[i];
            if (s != expect[i] && !(i == 1 && s == 3200000)) { positionalOK = false; break; }
        }
    }

    const float *x = 0, *W1 = 0, *W2 = 0, *dW1 = 0, *dW2 = 0, *db2 = 0;
    const float *atts1 = 0, *attd1 = 0, *b1 = 0, *atts2 = 0, *attd2 = 0, *b2 = 0, *db1 = 0;
    const int* ei = 0;

    if (positionalOK) {
        x     = (const float*)d_in[0];
        ei    = (const int*)  d_in[1];
        W1    = (const float*)d_in[2];
        atts1 = (const float*)d_in[3];
        attd1 = (const float*)d_in[4];
        b1    = (const float*)d_in[5];
        W2    = (const float*)d_in[6];
        atts2 = (const float*)d_in[7];
        attd2 = (const float*)d_in[8];
        b2    = (const float*)d_in[9];
        dW1   = (const float*)d_in[10];
        db1   = (const float*)d_in[11];
        dW2   = (const float*)d_in[12];
        db2   = (const float*)d_in[13];
    } else {
        const float* g256[3] = {0, 0, 0};
        const float* g64[4]  = {0, 0, 0, 0};
        int n256 = 0, n64 = 0;
        for (int i = 0; i < n_in; i++) {
            int s = in_sizes[i];
            const float* p = (const float*)d_in[i];
            if      (s == 6400000) x   = p;
            else if (s == 1600000 || s == 3200000) ei = (const int*)d_in[i];
            else if (s == 32768)   W1  = p;
            else if (s == 16384)   W2  = p;
            else if (s == 4096)    dW1 = p;
            else if (s == 8192)    dW2 = p;
            else if (s == 128)     db2 = p;
            else if (s == 256 && n256 < 3) g256[n256++] = p;
            else if (s == 64  && n64  < 4) g64[n64++]   = p;
        }
        bool dictLike = (n_in > 0 && in_sizes[0] == 6400000);
        atts1 = g256[dictLike ? 0 : 1];
        attd1 = g256[dictLike ? 1 : 0];
        b1    = g256[2];
        atts2 = g64[dictLike ? 0 : 1];
        attd2 = g64[dictLike ? 1 : 0];
        b2    = g64[2];
        db1   = g64[3];
        if (!x || !ei || !W1 || !W2 || !dW1 || !dW2 || !db2 || n256 < 3 || n64 < 4) {
            k_flag<<<1, 1>>>(z, 1e12f);
            return;
        }
    }

    k_detect<<<1, 32>>>(ei);

    // --- CSR build ---
    k_zero_deg<<<(NN + 255) / 256, 256>>>();
    k_count<<<(ET + 255) / 256, 256>>>(ei);
    k_scan_chunk<<<NCH, 512>>>();
    k_scan_mid<<<1, 32>>>();
    k_scan_add<<<NCH, 512>>>();
    k_scatter<<<(ET + 255) / 256, 256>>>(ei);

    // --- layer 1 ---
    {
        dim3 g(256 / 64, (NN + 127) / 128);
        k_gemm<<<g, 256>>>(x, W1, p_h1, NN, 128, 256);
    }
    k_att1<<<(NN * 32 + 255) / 256, 256>>>(atts1, attd1);
    k_agg1<<<(NN * 32 + 255) / 256, 256>>>(b1);

    // --- layer 2 ---
    {
        dim3 g(1, (NN + 127) / 128);
        k_gemm<<<g, 256>>>(p_h, W2, p_h2, NN, 256, 64);
    }
    k_att2<<<(NN * 32 + 255) / 256, 256>>>(atts2, attd2);
    k_agg2<<<(NN * 32 + 255) / 256, 256>>>(b2, z);

    // --- decoder ---
    if (xhat)
        k_decoder<<<1024, 128>>>(z, dW1, db1, dW2, db2, xhat);
}